// round 12
// baseline (speedup 1.0000x reference)
#include <cuda_runtime.h>
#include <cstdint>

// Fixed problem shape: N=320000, C=64, B=4, NY=496, NX=432, NZ=1
#define NY_   496
#define NX_   432
#define C_    64
#define B_    4
#define NCELL (B_ * NY_ * NX_)        // 857,088 cells

#define TX    48                      // cells per tile (432 = 9 * 48)
#define NTX   (NX_ / TX)              // 9 tiles per row
#define PAD   49                      // SMEM row pitch (48+1)

// Winner encoding: 0 = empty, w = point_index + 1.
// __device__ globals are zero-initialized at module load; each gather block
// re-zeroes its own winner segment after consuming it, so the array is
// all-zero at every kernel_launch entry (identical state -> deterministic).
__device__ int4 g_winner4[NCELL / 4];

// ---------------------------------------------------------------------------
// Kernel 1: atomicMax scatter of (point index + 1). Last-write-wins == max.
// coors rows: (b, z, y, x), z == 0 always (NZ=1).
// ---------------------------------------------------------------------------
__global__ void scatter_winner_kernel(const int* __restrict__ coors, int n) {
    int i = blockIdx.x * blockDim.x + threadIdx.x;
    if (i < n) {
        int4 cz = *reinterpret_cast<const int4*>(coors + 4 * i);
        int cell = (cz.x * NY_ + cz.z) * NX_ + cz.w;
        atomicMax(reinterpret_cast<int*>(g_winner4) + cell, i + 1);
    }
}

// ---------------------------------------------------------------------------
// Kernel 2: R5-proven tiled gather + transpose.
// One block = 48 cells along x (fixed b, y) x all 64 channels.
//   Phase 1: winners -> SMEM (12 int4), then reset them to 0 in GMEM.
//   Phase 2: 16 LANES COOPERATE PER CELL -> each warp-LDG touches only 4
//       128 B lines (coalesced 256 B row reads; nL=4, not 32). 3 f4/thread.
//   Phase 3: write 64 channels x 12 float4 coalesced STG.128 (192 B runs,
//       32 B sector-aligned -> no write amplification).
// SMEM: 64*49*4 + 48*4 = 12.7 KB -> 8 blocks/SM; block-level phase overlap
// hides load latency without explicit pipelining.
// ---------------------------------------------------------------------------
__global__ __launch_bounds__(256) void gather_tile_kernel(
    const float* __restrict__ feat, float* __restrict__ out) {

    __shared__ float tile[C_ * PAD];   // 12.25 KB
    __shared__ int   sw[TX];

    int t    = threadIdx.x;
    int bid  = blockIdx.x;                 // 0 .. B*NY*NTX-1 (17,856)
    int tx   = bid % NTX;
    int y    = (bid / NTX) % NY_;
    int b    = bid / (NTX * NY_);
    int x0   = tx * TX;
    int cell0 = (b * NY_ + y) * NX_ + x0;  // multiple of 16

    // Phase 1: load 48 winners (12 int4), then zero them for the next replay.
    if (t < TX / 4) {
        int4 w4 = g_winner4[cell0 / 4 + t];
        *reinterpret_cast<int4*>(sw + 4 * t) = w4;
        g_winner4[cell0 / 4 + t] = make_int4(0, 0, 0, 0);
    }
    __syncthreads();

    // Phase 2: 48 cells * 16 float4 = 768 loads, 3 per thread.
    // q -> (cell j = q/16, f4 = q%16). Lanes 0..15 share a cell => each
    // 256 B feature row is read in one fully-coalesced sweep, exactly once.
    #pragma unroll
    for (int k = 0; k < 3; k++) {
        int q  = k * 256 + t;
        int j  = q >> 4;
        int f4 = q & 15;
        int w  = sw[j];
        float4 v = make_float4(0.f, 0.f, 0.f, 0.f);
        if (w > 0) {
            v = *reinterpret_cast<const float4*>(
                feat + (size_t)(w - 1) * C_ + f4 * 4);
        }
        int c0 = f4 * 4;
        tile[(c0 + 0) * PAD + j] = v.x;
        tile[(c0 + 1) * PAD + j] = v.y;
        tile[(c0 + 2) * PAD + j] = v.z;
        tile[(c0 + 3) * PAD + j] = v.w;
    }
    __syncthreads();

    // Phase 3: 64 channels * 12 float4-groups = 768 vector stores, 3/thread.
    size_t obase = ((size_t)(b * C_) * NY_ + y) * NX_ + x0;   // 16 B aligned
    #pragma unroll
    for (int k = 0; k < 3; k++) {
        int idx = k * 256 + t;          // 0..767
        int c   = idx / (TX / 4);       // channel
        int g   = idx - c * (TX / 4);   // float4 group within the 48-run
        int j   = g * 4;
        const float* src = &tile[c * PAD + j];
        float4 v = make_float4(src[0], src[1], src[2], src[3]);
        *reinterpret_cast<float4*>(out + obase + (size_t)c * (NY_ * NX_) + j) = v;
    }
}

// ---------------------------------------------------------------------------
extern "C" void kernel_launch(void* const* d_in, const int* in_sizes, int n_in,
                              void* d_out, int out_size) {
    const float* feat  = (const float*)d_in[0];   // [N, 64] float32
    const int*   coors = (const int*)d_in[1];     // [N, 4] int32
    (void)n_in; (void)out_size;

    int n = in_sizes[1] / 4;

    {   // 1) atomicMax (point index + 1); winner array is all-zero on entry
        int threads = 256;
        int blocks  = (n + threads - 1) / threads;
        scatter_winner_kernel<<<blocks, threads>>>(coors, n);
    }
    {   // 2) tiled gather + transpose (+ winner reset for next replay)
        int blocks = B_ * NY_ * NTX;   // 17,856
        gather_tile_kernel<<<blocks, 256>>>(feat, (float*)d_out);
    }
}

// round 14
// speedup vs baseline: 1.1081x; 1.1081x over previous
#include <cuda_runtime.h>
#include <cstdint>

// Fixed problem shape: N=320000, C=64, B=4, NY=496, NX=432, NZ=1
#define NY_   496
#define NX_   432
#define C_    64
#define B_    4
#define NCELL (B_ * NY_ * NX_)        // 857,088 cells

#define RPB    2                      // y-rows per block
#define CELLS  (RPB * NX_)            // 864 cells per block
#define CCH    8                      // channels per chunk (8 chunks)
#define PITCH  868                    // SMEM pitch (864+4)
#define THREADS_G 512
#define NF4    (CELLS / 4)            // 216 float4 per channel

// Winner encoding: 0 = empty, w = point_index + 1.
// __device__ globals are zero-initialized at module load; each gather block
// re-zeroes its own winner segment after consuming it, so the array is
// all-zero at every kernel_launch entry (identical state -> deterministic).
__device__ int4 g_winner4[NCELL / 4];

// ---------------------------------------------------------------------------
// Kernel 1: atomicMax scatter of (point index + 1). Last-write-wins == max.
// coors rows: (b, z, y, x), z == 0 always (NZ=1).
// ---------------------------------------------------------------------------
__global__ void scatter_winner_kernel(const int* __restrict__ coors, int n) {
    int i = blockIdx.x * blockDim.x + threadIdx.x;
    if (i < n) {
        int4 cz = *reinterpret_cast<const int4*>(coors + 4 * i);
        int cell = (cz.x * NY_ + cz.z) * NX_ + cz.w;
        atomicMax(reinterpret_cast<int*>(g_winner4) + cell, i + 1);
    }
}

// ---------------------------------------------------------------------------
// Kernel 2: best-measured structure (RPB=2, CCH=8) + register prefetch
// pipelining + batched phase-3.
// One block = 864 contiguous cells (b, y-pair) x 64 channels, 8 chunks of 8.
//   Thread t owns cells t and t+512 (t<352). Chunk ci needs float4s
//   src[2ci], src[2ci+1] per cell; chunk ci+1's loads are issued right after
//   the STS->LDS sync so they overlap phase-3's LDS/STG stream.
//   Phase 3: per channel 3456 B contiguous (rows y0,y0+1 adjoin); 4 unrolled
//   iterations, addresses computed then 4 LDS.128 batched before 4 STG.128.
// Static SMEM: 864*4 + 8*868*4 = 31,232 B.
// ---------------------------------------------------------------------------
__global__ __launch_bounds__(THREADS_G) void gather_pair_kernel(
    const float* __restrict__ feat, float* __restrict__ out) {

    __shared__ int   sw[CELLS];            // 3.4 KB
    __shared__ float tile[CCH * PITCH];    // 27.8 KB

    int t = threadIdx.x;
    int p = blockIdx.x;                    // 0 .. B*NY/RPB-1  (992)
    int cell0 = p * CELLS;

    // Phase 0: winners -> SMEM (216 int4), then zero them for next replay.
    if (t < CELLS / 4) {
        int4 w4 = g_winner4[cell0 / 4 + t];
        *reinterpret_cast<int4*>(sw + 4 * t) = w4;
        g_winner4[cell0 / 4 + t] = make_int4(0, 0, 0, 0);
    }
    __syncthreads();

    int b  = p / (NY_ / RPB);
    int y0 = (p % (NY_ / RPB)) * RPB;
    size_t rowbase = ((size_t)(b * C_) * NY_ + y0) * NX_;

    bool hasB = (t + THREADS_G) < CELLS;   // t < 352
    const float4* srcA = nullptr;
    const float4* srcB = nullptr;
    {
        int wA = sw[t];
        if (wA > 0) srcA = reinterpret_cast<const float4*>(feat + (size_t)(wA - 1) * C_);
        if (hasB) {
            int wB = sw[t + THREADS_G];
            if (wB > 0) srcB = reinterpret_cast<const float4*>(feat + (size_t)(wB - 1) * C_);
        }
    }
    const float4 z4 = make_float4(0.f, 0.f, 0.f, 0.f);

    // Prefetch chunk 0 (overlaps winner-reset stores).
    float4 a0 = z4, a1 = z4, b0 = z4, b1 = z4;
    if (srcA) { a0 = srcA[0]; a1 = srcA[1]; }
    if (srcB) { b0 = srcB[0]; b1 = srcB[1]; }

    #pragma unroll
    for (int ci = 0; ci < C_ / CCH; ci++) {
        // Phase 2: register -> transposed SMEM (pure STS, no memory waits)
        {
            int j = t;
            tile[0 * PITCH + j] = a0.x;  tile[1 * PITCH + j] = a0.y;
            tile[2 * PITCH + j] = a0.z;  tile[3 * PITCH + j] = a0.w;
            tile[4 * PITCH + j] = a1.x;  tile[5 * PITCH + j] = a1.y;
            tile[6 * PITCH + j] = a1.z;  tile[7 * PITCH + j] = a1.w;
        }
        if (hasB) {
            int j = t + THREADS_G;
            tile[0 * PITCH + j] = b0.x;  tile[1 * PITCH + j] = b0.y;
            tile[2 * PITCH + j] = b0.z;  tile[3 * PITCH + j] = b0.w;
            tile[4 * PITCH + j] = b1.x;  tile[5 * PITCH + j] = b1.y;
            tile[6 * PITCH + j] = b1.z;  tile[7 * PITCH + j] = b1.w;
        }
        __syncthreads();

        // Prefetch chunk ci+1: LDGs fly concurrently with phase 3 below.
        float4 na0 = z4, na1 = z4, nb0 = z4, nb1 = z4;
        if (ci + 1 < C_ / CCH) {
            if (srcA) { na0 = srcA[2 * ci + 2]; na1 = srcA[2 * ci + 3]; }
            if (srcB) { nb0 = srcB[2 * ci + 2]; nb1 = srcB[2 * ci + 3]; }
        }

        // Phase 3: 8 channels * 216 float4 = 1728 stores.
        // Batch: compute 4 addresses, 4 LDS.128, then 4 STG.128 (MLP=4).
        {
            int cc = ci * CCH;
            int q0 = t, q1 = t + 512, q2 = t + 1024, q3 = t + 1536;
            int k0 = q0 / NF4, g0 = q0 - k0 * NF4;
            int k1 = q1 / NF4, g1 = q1 - k1 * NF4;
            int k2 = q2 / NF4, g2 = q2 - k2 * NF4;
            int k3 = q3 / NF4, g3 = q3 - k3 * NF4;
            bool p3 = (q3 < CCH * NF4);   // t < 192
            float4 v0 = *reinterpret_cast<const float4*>(&tile[k0 * PITCH + g0 * 4]);
            float4 v1 = *reinterpret_cast<const float4*>(&tile[k1 * PITCH + g1 * 4]);
            float4 v2 = *reinterpret_cast<const float4*>(&tile[k2 * PITCH + g2 * 4]);
            float4 v3 = p3 ? *reinterpret_cast<const float4*>(&tile[k3 * PITCH + g3 * 4]) : z4;
            *reinterpret_cast<float4*>(out + rowbase + (size_t)(cc + k0) * (NY_ * NX_) + g0 * 4) = v0;
            *reinterpret_cast<float4*>(out + rowbase + (size_t)(cc + k1) * (NY_ * NX_) + g1 * 4) = v1;
            *reinterpret_cast<float4*>(out + rowbase + (size_t)(cc + k2) * (NY_ * NX_) + g2 * 4) = v2;
            if (p3)
                *reinterpret_cast<float4*>(out + rowbase + (size_t)(cc + k3) * (NY_ * NX_) + g3 * 4) = v3;
        }
        __syncthreads();

        a0 = na0; a1 = na1; b0 = nb0; b1 = nb1;
    }
}

// ---------------------------------------------------------------------------
extern "C" void kernel_launch(void* const* d_in, const int* in_sizes, int n_in,
                              void* d_out, int out_size) {
    const float* feat  = (const float*)d_in[0];   // [N, 64] float32
    const int*   coors = (const int*)d_in[1];     // [N, 4] int32
    (void)n_in; (void)out_size;

    int n = in_sizes[1] / 4;

    {   // 1) atomicMax (point index + 1); winner array is all-zero on entry
        int threads = 256;
        int blocks  = (n + threads - 1) / threads;
        scatter_winner_kernel<<<blocks, threads>>>(coors, n);
    }
    {   // 2) pipelined pair gather + transpose (+ winner reset)
        int blocks = B_ * NY_ / RPB;   // 992
        gather_pair_kernel<<<blocks, THREADS_G>>>(feat, (float*)d_out);
    }
}

// round 15
// speedup vs baseline: 1.3012x; 1.1743x over previous
#include <cuda_runtime.h>
#include <cstdint>

// Fixed problem shape: N=320000, C=64, B=4, NY=496, NX=432, NZ=1
#define NY_   496
#define NX_   432
#define C_    64
#define B_    4
#define NCELL (B_ * NY_ * NX_)        // 857,088 cells

#define RPB    2                      // y-rows per block
#define CELLS  (RPB * NX_)            // 864 cells per block
#define CCH    8                      // channels per chunk (8 chunks)
#define PITCH  868                    // SMEM pitch (864+4)
#define THREADS_G 512
#define NF4    (CELLS / 4)            // 216 float4 per channel

// Winner encoding: 0 = empty, w = point_index + 1.
// __device__ globals are zero-initialized at module load; each gather block
// re-zeroes its own winner segment after consuming it, so the array is
// all-zero at every kernel_launch entry (identical state -> deterministic).
__device__ int4 g_winner4[NCELL / 4];

// ---------------------------------------------------------------------------
// Kernel 1: atomicMax scatter of (point index + 1). Last-write-wins == max.
// coors rows: (b, z, y, x), z == 0 always (NZ=1).
// ---------------------------------------------------------------------------
__global__ void scatter_winner_kernel(const int* __restrict__ coors, int n) {
    int i = blockIdx.x * blockDim.x + threadIdx.x;
    if (i < n) {
        int4 cz = *reinterpret_cast<const int4*>(coors + 4 * i);
        int cell = (cz.x * NY_ + cz.z) * NX_ + cz.w;
        atomicMax(reinterpret_cast<int*>(g_winner4) + cell, i + 1);
    }
}

// ---------------------------------------------------------------------------
// Kernel 2: measured-best structure (R7: RPB=2, CCH=8, thread=cell, simple
// loops) with ONE change: phase-2 loads for both owned cells are hoisted
// ahead of all STS, so each thread has 4 LDG.128 in flight (MLP 2 -> 4)
// before the first dependent shared store.
// Static SMEM: 864*4 + 8*868*4 = 31,232 B.
// ---------------------------------------------------------------------------
__global__ __launch_bounds__(THREADS_G) void gather_pair_kernel(
    const float* __restrict__ feat, float* __restrict__ out) {

    __shared__ int   sw[CELLS];            // 3.4 KB
    __shared__ float tile[CCH * PITCH];    // 27.8 KB

    int t = threadIdx.x;
    int p = blockIdx.x;                    // 0 .. B*NY/RPB-1  (992)
    int cell0 = p * CELLS;

    // Phase 0: winners -> SMEM (216 int4), then zero them for next replay.
    if (t < CELLS / 4) {
        int4 w4 = g_winner4[cell0 / 4 + t];
        *reinterpret_cast<int4*>(sw + 4 * t) = w4;
        g_winner4[cell0 / 4 + t] = make_int4(0, 0, 0, 0);
    }
    __syncthreads();

    int b  = p / (NY_ / RPB);
    int y0 = (p % (NY_ / RPB)) * RPB;
    size_t rowbase = ((size_t)(b * C_) * NY_ + y0) * NX_;

    // Per-thread cell ownership: cell t (all threads), cell t+512 (t<352).
    bool hasB = (t + THREADS_G) < CELLS;
    const float4* srcA = nullptr;
    const float4* srcB = nullptr;
    {
        int wA = sw[t];
        if (wA > 0) srcA = reinterpret_cast<const float4*>(feat + (size_t)(wA - 1) * C_);
        if (hasB) {
            int wB = sw[t + THREADS_G];
            if (wB > 0) srcB = reinterpret_cast<const float4*>(feat + (size_t)(wB - 1) * C_);
        }
    }
    const float4 z4 = make_float4(0.f, 0.f, 0.f, 0.f);

    #pragma unroll
    for (int ci = 0; ci < C_ / CCH; ci++) {
        // Phase 2: hoist all 4 loads (MLP=4), then pure STS transpose.
        float4 a0 = z4, a1 = z4, b0 = z4, b1 = z4;
        if (srcA) { a0 = srcA[2 * ci]; a1 = srcA[2 * ci + 1]; }
        if (srcB) { b0 = srcB[2 * ci]; b1 = srcB[2 * ci + 1]; }

        {
            int j = t;
            tile[0 * PITCH + j] = a0.x;  tile[1 * PITCH + j] = a0.y;
            tile[2 * PITCH + j] = a0.z;  tile[3 * PITCH + j] = a0.w;
            tile[4 * PITCH + j] = a1.x;  tile[5 * PITCH + j] = a1.y;
            tile[6 * PITCH + j] = a1.z;  tile[7 * PITCH + j] = a1.w;
        }
        if (hasB) {
            int j = t + THREADS_G;
            tile[0 * PITCH + j] = b0.x;  tile[1 * PITCH + j] = b0.y;
            tile[2 * PITCH + j] = b0.z;  tile[3 * PITCH + j] = b0.w;
            tile[4 * PITCH + j] = b1.x;  tile[5 * PITCH + j] = b1.y;
            tile[6 * PITCH + j] = b1.z;  tile[7 * PITCH + j] = b1.w;
        }
        __syncthreads();

        // Phase 3: 8 channels * 216 float4 = 1728 vector stores (q-loop,
        // NF4 is a compile-time constant -> div becomes mul-shift).
        int cc = ci * CCH;
        for (int q = t; q < CCH * NF4; q += THREADS_G) {
            int k = q / NF4;
            int g = q - k * NF4;
            float4 v = *reinterpret_cast<const float4*>(&tile[k * PITCH + g * 4]);
            *reinterpret_cast<float4*>(
                out + rowbase + (size_t)(cc + k) * (NY_ * NX_) + g * 4) = v;
        }
        __syncthreads();
    }
}

// ---------------------------------------------------------------------------
extern "C" void kernel_launch(void* const* d_in, const int* in_sizes, int n_in,
                              void* d_out, int out_size) {
    const float* feat  = (const float*)d_in[0];   // [N, 64] float32
    const int*   coors = (const int*)d_in[1];     // [N, 4] int32
    (void)n_in; (void)out_size;

    int n = in_sizes[1] / 4;

    {   // 1) atomicMax (point index + 1); winner array is all-zero on entry
        int threads = 256;
        int blocks  = (n + threads - 1) / threads;
        scatter_winner_kernel<<<blocks, threads>>>(coors, n);
    }
    {   // 2) pair gather + transpose (+ winner reset)
        int blocks = B_ * NY_ / RPB;   // 992
        gather_pair_kernel<<<blocks, THREADS_G>>>(feat, (float*)d_out);
    }
}